// round 14
// baseline (speedup 1.0000x reference)
#include <cuda_runtime.h>
#include <cuda_fp16.h>
#include <math.h>
#include <stdint.h>

// ---------------- problem constants ----------------
#define D_MODEL 768
#define D_HID   3072
#define NE      8
#define NTOK    2048
#define NASSIGN (NTOK*2)             // 4096
#define BM 128
#define BN 128
#define BK 32
#define MAXM     (NASSIGN + NE*BM)   // 5120
#define MAXTILES (NASSIGN/BM + NE)   // 40

// ---------------- smem layout (bytes, per buffer) ----------------
#define PA 80                        // A row pitch (32 fp16 = 64B data + 16B pad)
#define PB 272                       // B row pitch (128 fp16 = 256B data + 16B pad)
#define ST_B   (128*PA)              // 10240
#define STAGE_SZ (128*PA + 32*PB)    // 18944
#define SMEM_DYN (2*STAGE_SZ)        // 37888  (2 CTAs/SM)

// ---------------- scratch ----------------
__device__ int    g_counts[NE];
__device__ int    g_tile_e[MAXTILES];
__device__ int    g_tile_m0[MAXTILES];
__device__ int    g_ntiles;
__device__ int    g_expert_of[NASSIGN];
__device__ float  g_w_of[NASSIGN];
__device__ int    g_tok[MAXM];
__device__ float  g_wt[MAXM];
__device__ __align__(256) __half g_xh[(size_t)NTOK * D_MODEL];
__device__ __align__(256) __half g_hh[(size_t)MAXM * D_HID];

// ---------------- helpers ----------------
__device__ __forceinline__ uint32_t smem_u32(const void* p) {
    uint32_t a;
    asm("{ .reg .u64 t; cvta.to.shared.u64 t, %1; cvt.u32.u64 %0, t; }" : "=r"(a) : "l"(p));
    return a;
}
__device__ __forceinline__ void sts128(uint32_t addr, uint4 v) {
    asm volatile("st.shared.v4.b32 [%0], {%1, %2, %3, %4};"
                 :: "r"(addr), "r"(v.x), "r"(v.y), "r"(v.z), "r"(v.w) : "memory");
}
__device__ __forceinline__ void ldsm4(uint32_t* r, uint32_t addr) {
    asm volatile("ldmatrix.sync.aligned.m8n8.x4.shared.b16 {%0,%1,%2,%3}, [%4];"
                 : "=r"(r[0]), "=r"(r[1]), "=r"(r[2]), "=r"(r[3]) : "r"(addr));
}
__device__ __forceinline__ void ldsm4t(uint32_t* r, uint32_t addr) {
    asm volatile("ldmatrix.sync.aligned.m8n8.x4.trans.shared.b16 {%0,%1,%2,%3}, [%4];"
                 : "=r"(r[0]), "=r"(r[1]), "=r"(r[2]), "=r"(r[3]) : "r"(addr));
}
__device__ __forceinline__ void mma16816(float* d, const uint32_t* a, const uint32_t* b) {
    asm volatile("mma.sync.aligned.m16n8k16.row.col.f32.f16.f16.f32 "
                 "{%0,%1,%2,%3}, {%4,%5,%6,%7}, {%8,%9}, {%0,%1,%2,%3};"
                 : "+f"(d[0]), "+f"(d[1]), "+f"(d[2]), "+f"(d[3])
                 : "r"(a[0]), "r"(a[1]), "r"(a[2]), "r"(a[3]), "r"(b[0]), "r"(b[1]));
}
__device__ __forceinline__ float gelu_erf(float v) {
    return 0.5f * v * (1.0f + erff(v * 0.7071067811865476f));
}
__device__ __forceinline__ uint32_t pk(float a, float b) {
    __half2 h = __floats2half2_rn(a, b);
    uint32_t u; memcpy(&u, &h, 4); return u;
}

// ---------------- prepass: x -> fp16; zero d_out; zero router counters ----------------
__global__ __launch_bounds__(256) void convert_x_kernel(const float* __restrict__ x,
                                                        float* __restrict__ out) {
    int i = blockIdx.x * blockDim.x + threadIdx.x;
    if (i < NE) g_counts[i] = 0;
    if (i >= NTOK * D_MODEL / 4) return;
    float4 v = ((const float4*)x)[i];
    ((__half2*)g_xh)[2 * i]     = __floats2half2_rn(v.x, v.y);
    ((__half2*)g_xh)[2 * i + 1] = __floats2half2_rn(v.z, v.w);
    ((float4*)out)[i] = make_float4(0.f, 0.f, 0.f, 0.f);
}

// ---------------- router ----------------
__global__ __launch_bounds__(256) void router_kernel(const float* __restrict__ x,
                                                     const float* __restrict__ gate_w) {
    int warp = (blockIdx.x * blockDim.x + threadIdx.x) >> 5;
    int lane = threadIdx.x & 31;
    if (warp >= NTOK) return;
    const float* xr = x + (size_t)warp * D_MODEL;
    float acc[NE];
#pragma unroll
    for (int e = 0; e < NE; e++) acc[e] = 0.f;
    for (int d = lane; d < D_MODEL; d += 32) {
        float xv = xr[d];
        const float4* gw = (const float4*)(gate_w + (size_t)d * NE);
        float4 a = gw[0], b = gw[1];
        acc[0] = fmaf(xv, a.x, acc[0]); acc[1] = fmaf(xv, a.y, acc[1]);
        acc[2] = fmaf(xv, a.z, acc[2]); acc[3] = fmaf(xv, a.w, acc[3]);
        acc[4] = fmaf(xv, b.x, acc[4]); acc[5] = fmaf(xv, b.y, acc[5]);
        acc[6] = fmaf(xv, b.z, acc[6]); acc[7] = fmaf(xv, b.w, acc[7]);
    }
#pragma unroll
    for (int e = 0; e < NE; e++)
#pragma unroll
        for (int o = 16; o > 0; o >>= 1)
            acc[e] += __shfl_xor_sync(0xffffffffu, acc[e], o);
    if (lane == 0) {
        float mx = acc[0];
#pragma unroll
        for (int e = 1; e < NE; e++) mx = fmaxf(mx, acc[e]);
        float p[NE]; float s = 0.f;
#pragma unroll
        for (int e = 0; e < NE; e++) { p[e] = expf(acc[e] - mx); s += p[e]; }
        float inv = 1.0f / s;
#pragma unroll
        for (int e = 0; e < NE; e++) p[e] *= inv;
        int i0 = 0;
#pragma unroll
        for (int e = 1; e < NE; e++) if (p[e] > p[i0]) i0 = e;
        int i1 = (i0 == 0) ? 1 : 0;
#pragma unroll
        for (int e = 0; e < NE; e++) if (e != i0 && p[e] > p[i1]) i1 = e;
        float w0 = p[i0], w1 = p[i1];
        float isw = 1.0f / (w0 + w1);
        g_expert_of[warp * 2 + 0] = i0;
        g_expert_of[warp * 2 + 1] = i1;
        g_w_of[warp * 2 + 0] = w0 * isw;
        g_w_of[warp * 2 + 1] = w1 * isw;
        atomicAdd(&g_counts[i0], 1);
        atomicAdd(&g_counts[i1], 1);
    }
}

// ---------------- fused setup + scatter (single block, smem cursors) ----------------
__global__ __launch_bounds__(256) void setup_scatter_kernel() {
    __shared__ int s_cur[NE];
    int tid = threadIdx.x;
    if (tid == 0) {
        int off = 0, t = 0;
        for (int e = 0; e < NE; e++) {
            s_cur[e] = off;
            int nt = (g_counts[e] + BM - 1) / BM;
            for (int i = 0; i < nt; i++) { g_tile_e[t] = e; g_tile_m0[t] = off + i * BM; t++; }
            off += nt * BM;
        }
        g_ntiles = t;
    }
    __syncthreads();
    for (int i = tid; i < MAXM; i += 256) { g_tok[i] = -1; g_wt[i] = 0.f; }
    __syncthreads();
    for (int idx = tid; idx < NASSIGN; idx += 256) {
        int e = g_expert_of[idx];
        int slot = atomicAdd(&s_cur[e], 1);
        g_tok[slot] = idx >> 1;
        g_wt[slot] = g_w_of[idx];
    }
}

// ---------------- grouped GEMM: fp32 weights converted in copy stage ----------------
template<bool G1, int KTOT, int NWID, int SPLIT>
__global__ __launch_bounds__(256) void moe_gemm(const float* __restrict__ Wsrc,
                                                const float* __restrict__ bias,
                                                float* __restrict__ out) {
    int tile = blockIdx.y;
    if (tile >= g_ntiles) return;
    int e  = g_tile_e[tile];
    int m0 = g_tile_m0[tile];
    int n0 = blockIdx.x * BN;
    const float* W = Wsrc + (size_t)e * KTOT * NWID;

    extern __shared__ char smem[];
    uint32_t sb = smem_u32(smem);
    __shared__ int   s_tok[BM];
    __shared__ float s_wt[BM];

    int tid = threadIdx.x, lane = tid & 31, wid = tid >> 5;
    int wm = wid >> 2, wn = wid & 3;

    if (tid < BM) { s_tok[tid] = g_tok[m0 + tid]; s_wt[tid] = g_wt[m0 + tid]; }
    __syncthreads();

    // A copy: rows ar, ar+64; one uint4 (16B fp16) per row at col aq
    const int aq = tid & 3, ar = tid >> 2;
    // B copy (fp32): k-row bk32 = tid>>3 (0..31), segment sg = tid&7 (64B fp32 each)
    const int sg = tid & 7, bk32 = tid >> 3;

    const char* aHp[2];
    bool av[2];
#pragma unroll
    for (int r = 0; r < 2; r++) {
        int row = ar + 64 * r;
        if (G1) {
            int tok = s_tok[row];
            av[r] = (tok >= 0);
            aHp[r] = (const char*)g_xh + (size_t)(tok < 0 ? 0 : tok) * KTOT * 2;
        } else {
            av[r] = true;
            aHp[r] = (const char*)g_hh + (size_t)(m0 + row) * KTOT * 2;
        }
    }
    const float* bP = W + (size_t)bk32 * NWID + n0 + sg * 16;

    uint4 pah[2];
    float4 pbf[4];
    const uint4 z4 = make_uint4(0, 0, 0, 0);
    const int NCHL = KTOT / BK / SPLIT;
    const int kc0  = (SPLIT > 1) ? blockIdx.z * NCHL : 0;

    auto load_chunk = [&](int kci) {
        size_t ko = (size_t)(kc0 + kci) * 64 + aq * 16;
#pragma unroll
        for (int r = 0; r < 2; r++)
            pah[r] = av[r] ? *(const uint4*)(aHp[r] + ko) : z4;
        const float* bs = bP + (size_t)(kc0 + kci) * BK * NWID;
#pragma unroll
        for (int r = 0; r < 4; r++)
            pbf[r] = *(const float4*)(bs + r * 4);
    };
    auto store_chunk = [&](int buf) {
        uint32_t base = sb + buf * STAGE_SZ;
#pragma unroll
        for (int r = 0; r < 2; r++)
            sts128(base + (uint32_t)(ar + 64 * r) * PA + aq * 16, pah[r]);
        uint4 h0, h1;
        h0.x = pk(pbf[0].x, pbf[0].y); h0.y = pk(pbf[0].z, pbf[0].w);
        h0.z = pk(pbf[1].x, pbf[1].y); h0.w = pk(pbf[1].z, pbf[1].w);
        h1.x = pk(pbf[2].x, pbf[2].y); h1.y = pk(pbf[2].z, pbf[2].w);
        h1.z = pk(pbf[3].x, pbf[3].y); h1.w = pk(pbf[3].z, pbf[3].w);
        uint32_t boff = base + ST_B + (uint32_t)bk32 * PB + sg * 32;
        sts128(boff, h0);
        sts128(boff + 16, h1);
    };

    float acc[4][4][4];
#pragma unroll
    for (int i = 0; i < 4; i++)
#pragma unroll
        for (int j = 0; j < 4; j++)
#pragma unroll
            for (int k = 0; k < 4; k++) acc[i][j][k] = 0.f;

    load_chunk(0);
    store_chunk(0);
    __syncthreads();

#pragma unroll 1
    for (int kc = 0; kc < NCHL; kc++) {
        bool more = (kc + 1 < NCHL);
        if (more) load_chunk(kc + 1);

        uint32_t base = sb + (kc & 1) * STAGE_SZ;
#pragma unroll
        for (int kf = 0; kf < 2; kf++) {
            uint32_t ah[4][4], bh[4][2];
#pragma unroll
            for (int mf = 0; mf < 4; mf++) {
                uint32_t arr = wm * 64 + mf * 16 + (lane & 15);
                ldsm4(ah[mf], base + arr * PA + kf * 32 + ((lane >> 4) << 4));
            }
#pragma unroll
            for (int p = 0; p < 2; p++) {
                uint32_t kr = kf * 16 + (lane & 15);
                uint32_t boff = kr * PB + (wn * 32 + p * 16 + ((lane >> 4) << 3)) * 2;
                uint32_t t[4];
                ldsm4t(t, base + ST_B + boff);
                bh[2 * p][0] = t[0]; bh[2 * p][1] = t[1];
                bh[2 * p + 1][0] = t[2]; bh[2 * p + 1][1] = t[3];
            }
#pragma unroll
            for (int mf = 0; mf < 4; mf++)
#pragma unroll
                for (int nf = 0; nf < 4; nf++)
                    mma16816(acc[mf][nf], ah[mf], bh[nf]);
        }
        if (more) store_chunk((kc + 1) & 1);
        __syncthreads();
    }

    // ---- epilogue ----
    int rb = wm * 64 + (lane >> 2);
    int cb = wn * 32 + (lane & 3) * 2;
    const float* be = bias + (size_t)e * NWID + n0;
    bool addb = (SPLIT == 1) || (blockIdx.z == 0);
#pragma unroll
    for (int mf = 0; mf < 4; mf++) {
#pragma unroll
        for (int h = 0; h < 2; h++) {
            int mloc = rb + mf * 16 + h * 8;
            int m = m0 + mloc;
            if (G1) {
                __half2* hrow = (__half2*)(g_hh + (size_t)m * NWID + n0);
#pragma unroll
                for (int nf = 0; nf < 4; nf++) {
                    int c = cb + nf * 8;
                    float2 bb = *(const float2*)(be + c);
                    float v0 = gelu_erf(acc[mf][nf][2 * h + 0] + bb.x);
                    float v1 = gelu_erf(acc[mf][nf][2 * h + 1] + bb.y);
                    hrow[c >> 1] = __floats2half2_rn(v0, v1);
                }
            } else {
                float wt = s_wt[mloc];
                if (wt != 0.f) {
                    int tok = s_tok[mloc];
                    float* orow = out + (size_t)tok * NWID + n0;
#pragma unroll
                    for (int nf = 0; nf < 4; nf++) {
                        int c = cb + nf * 8;
                        float bx = addb ? be[c] : 0.f, by = addb ? be[c + 1] : 0.f;
                        atomicAdd(orow + c,     wt * (acc[mf][nf][2 * h + 0] + bx));
                        atomicAdd(orow + c + 1, wt * (acc[mf][nf][2 * h + 1] + by));
                    }
                }
            }
        }
    }
}

// ---------------- launch ----------------
extern "C" void kernel_launch(void* const* d_in, const int* in_sizes, int n_in,
                              void* d_out, int out_size) {
    const float* x      = (const float*)d_in[0];
    const float* gate_w = (const float*)d_in[1];
    const float* w1     = (const float*)d_in[2];
    const float* b1     = (const float*)d_in[3];
    const float* w2     = (const float*)d_in[4];
    const float* b2     = (const float*)d_in[5];
    float* out = (float*)d_out;

    cudaFuncSetAttribute(moe_gemm<true,  D_MODEL, D_HID, 1>,
                         cudaFuncAttributeMaxDynamicSharedMemorySize, SMEM_DYN);
    cudaFuncSetAttribute(moe_gemm<false, D_HID, D_MODEL, 4>,
                         cudaFuncAttributeMaxDynamicSharedMemorySize, SMEM_DYN);

    convert_x_kernel<<<(NTOK * D_MODEL / 4 + 255) / 256, 256>>>(x, out);
    router_kernel<<<NTOK / 8, 256>>>(x, gate_w);
    setup_scatter_kernel<<<1, 256>>>();
    moe_gemm<true,  D_MODEL, D_HID, 1>
        <<<dim3(D_HID / BN, MAXTILES, 1), 256, SMEM_DYN>>>(w1, b1, out);
    moe_gemm<false, D_HID, D_MODEL, 4>
        <<<dim3(D_MODEL / BN, MAXTILES, 4), 256, SMEM_DYN>>>(w2, b2, out);
}

// round 15
// speedup vs baseline: 1.0249x; 1.0249x over previous
#include <cuda_runtime.h>
#include <cuda_fp16.h>
#include <math.h>
#include <stdint.h>

// ---------------- problem constants ----------------
#define D_MODEL 768
#define D_HID   3072
#define NE      8
#define NTOK    2048
#define NASSIGN (NTOK*2)             // 4096
#define BM 128
#define BN 256
#define BK 32
#define MAXM     (NASSIGN + NE*BM)   // 5120
#define MAXTILES (NASSIGN/BM + NE)   // 40

// ---------------- smem layout (bytes, per buffer) ----------------
#define PA 80                        // A row pitch (32 fp16 = 64B data + 16B pad)
#define PB 528                       // B row pitch (256 fp16 = 512B data + 16B pad)
#define ST_B   (128*PA)              // 10240
#define STAGE_SZ (128*PA + 32*PB)    // 27136
#define SMEM_DYN (2*STAGE_SZ)        // 54272

// ---------------- scratch ----------------
__device__ int    g_counts[NE];
__device__ int    g_tile_e[MAXTILES];
__device__ int    g_tile_m0[MAXTILES];
__device__ int    g_ntiles;
__device__ int    g_expert_of[NASSIGN];
__device__ float  g_w_of[NASSIGN];
__device__ int    g_tok[MAXM];
__device__ float  g_wt[MAXM];
__device__ __align__(256) __half g_xh[(size_t)NTOK * D_MODEL];
__device__ __align__(256) __half g_w1h[(size_t)NE * D_MODEL * D_HID];
__device__ __align__(256) __half g_w2h[(size_t)NE * D_HID * D_MODEL];
__device__ __align__(256) __half g_hh[(size_t)MAXM * D_HID];

// ---------------- helpers ----------------
__device__ __forceinline__ uint32_t smem_u32(const void* p) {
    uint32_t a;
    asm("{ .reg .u64 t; cvta.to.shared.u64 t, %1; cvt.u32.u64 %0, t; }" : "=r"(a) : "l"(p));
    return a;
}
__device__ __forceinline__ void sts128(uint32_t addr, uint4 v) {
    asm volatile("st.shared.v4.b32 [%0], {%1, %2, %3, %4};"
                 :: "r"(addr), "r"(v.x), "r"(v.y), "r"(v.z), "r"(v.w) : "memory");
}
__device__ __forceinline__ void ldsm4(uint32_t* r, uint32_t addr) {
    asm volatile("ldmatrix.sync.aligned.m8n8.x4.shared.b16 {%0,%1,%2,%3}, [%4];"
                 : "=r"(r[0]), "=r"(r[1]), "=r"(r[2]), "=r"(r[3]) : "r"(addr));
}
__device__ __forceinline__ void ldsm4t(uint32_t* r, uint32_t addr) {
    asm volatile("ldmatrix.sync.aligned.m8n8.x4.trans.shared.b16 {%0,%1,%2,%3}, [%4];"
                 : "=r"(r[0]), "=r"(r[1]), "=r"(r[2]), "=r"(r[3]) : "r"(addr));
}
__device__ __forceinline__ void mma16816(float* d, const uint32_t* a, const uint32_t* b) {
    asm volatile("mma.sync.aligned.m16n8k16.row.col.f32.f16.f16.f32 "
                 "{%0,%1,%2,%3}, {%4,%5,%6,%7}, {%8,%9}, {%0,%1,%2,%3};"
                 : "+f"(d[0]), "+f"(d[1]), "+f"(d[2]), "+f"(d[3])
                 : "r"(a[0]), "r"(a[1]), "r"(a[2]), "r"(a[3]), "r"(b[0]), "r"(b[1]));
}
__device__ __forceinline__ float gelu_erf(float v) {
    return 0.5f * v * (1.0f + erff(v * 0.7071067811865476f));
}

// ---------------- prepass: both weights -> fp16 in ONE launch ----------------
__global__ __launch_bounds__(256) void convert_w_kernel(const float* __restrict__ w1,
                                                        const float* __restrict__ w2, int n4) {
    int i = blockIdx.x * blockDim.x + threadIdx.x;
    const float* src;
    __half* dst;
    int j;
    if (i < n4) { src = w1; dst = g_w1h; j = i; }
    else if (i < 2 * n4) { src = w2; dst = g_w2h; j = i - n4; }
    else return;
    float4 v = ((const float4*)src)[j];
    ((__half2*)dst)[2 * j]     = __floats2half2_rn(v.x, v.y);
    ((__half2*)dst)[2 * j + 1] = __floats2half2_rn(v.z, v.w);
}

// x -> fp16; zero d_out; zero router counters (runs FIRST)
__global__ __launch_bounds__(256) void convert_x_kernel(const float* __restrict__ x,
                                                        float* __restrict__ out) {
    int i = blockIdx.x * blockDim.x + threadIdx.x;
    if (i < NE) g_counts[i] = 0;
    if (i >= NTOK * D_MODEL / 4) return;
    float4 v = ((const float4*)x)[i];
    ((__half2*)g_xh)[2 * i]     = __floats2half2_rn(v.x, v.y);
    ((__half2*)g_xh)[2 * i + 1] = __floats2half2_rn(v.z, v.w);
    ((float4*)out)[i] = make_float4(0.f, 0.f, 0.f, 0.f);
}

// ---------------- router ----------------
__global__ __launch_bounds__(256) void router_kernel(const float* __restrict__ x,
                                                     const float* __restrict__ gate_w) {
    int warp = (blockIdx.x * blockDim.x + threadIdx.x) >> 5;
    int lane = threadIdx.x & 31;
    if (warp >= NTOK) return;
    const float* xr = x + (size_t)warp * D_MODEL;
    float acc[NE];
#pragma unroll
    for (int e = 0; e < NE; e++) acc[e] = 0.f;
    for (int d = lane; d < D_MODEL; d += 32) {
        float xv = xr[d];
        const float4* gw = (const float4*)(gate_w + (size_t)d * NE);
        float4 a = gw[0], b = gw[1];
        acc[0] = fmaf(xv, a.x, acc[0]); acc[1] = fmaf(xv, a.y, acc[1]);
        acc[2] = fmaf(xv, a.z, acc[2]); acc[3] = fmaf(xv, a.w, acc[3]);
        acc[4] = fmaf(xv, b.x, acc[4]); acc[5] = fmaf(xv, b.y, acc[5]);
        acc[6] = fmaf(xv, b.z, acc[6]); acc[7] = fmaf(xv, b.w, acc[7]);
    }
#pragma unroll
    for (int e = 0; e < NE; e++)
#pragma unroll
        for (int o = 16; o > 0; o >>= 1)
            acc[e] += __shfl_xor_sync(0xffffffffu, acc[e], o);
    if (lane == 0) {
        float mx = acc[0];
#pragma unroll
        for (int e = 1; e < NE; e++) mx = fmaxf(mx, acc[e]);
        float p[NE]; float s = 0.f;
#pragma unroll
        for (int e = 0; e < NE; e++) { p[e] = expf(acc[e] - mx); s += p[e]; }
        float inv = 1.0f / s;
#pragma unroll
        for (int e = 0; e < NE; e++) p[e] *= inv;
        int i0 = 0;
#pragma unroll
        for (int e = 1; e < NE; e++) if (p[e] > p[i0]) i0 = e;
        int i1 = (i0 == 0) ? 1 : 0;
#pragma unroll
        for (int e = 0; e < NE; e++) if (e != i0 && p[e] > p[i1]) i1 = e;
        float w0 = p[i0], w1 = p[i1];
        float isw = 1.0f / (w0 + w1);
        g_expert_of[warp * 2 + 0] = i0;
        g_expert_of[warp * 2 + 1] = i1;
        g_w_of[warp * 2 + 0] = w0 * isw;
        g_w_of[warp * 2 + 1] = w1 * isw;
        atomicAdd(&g_counts[i0], 1);
        atomicAdd(&g_counts[i1], 1);
    }
}

// ---------------- fused setup + scatter (single block, smem cursors) ----------------
__global__ __launch_bounds__(256) void setup_scatter_kernel() {
    __shared__ int s_cur[NE];
    int tid = threadIdx.x;
    if (tid == 0) {
        int off = 0, t = 0;
        for (int e = 0; e < NE; e++) {
            s_cur[e] = off;
            int nt = (g_counts[e] + BM - 1) / BM;
            for (int i = 0; i < nt; i++) { g_tile_e[t] = e; g_tile_m0[t] = off + i * BM; t++; }
            off += nt * BM;
        }
        g_ntiles = t;
    }
    __syncthreads();
    for (int i = tid; i < MAXM; i += 256) { g_tok[i] = -1; g_wt[i] = 0.f; }
    __syncthreads();
    for (int idx = tid; idx < NASSIGN; idx += 256) {
        int e = g_expert_of[idx];
        int slot = atomicAdd(&s_cur[e], 1);
        g_tok[slot] = idx >> 1;
        g_wt[slot] = g_w_of[idx];
    }
}

// ---------------- grouped GEMM: 128x256 tile, 8 warps @ 64x64, fp16 prepass ----------------
template<bool G1, int KTOT, int NWID, int SPLIT>
__global__ __launch_bounds__(256, 1) void moe_gemm(const float* __restrict__ bias,
                                                   float* __restrict__ out) {
    int tile = blockIdx.y;
    if (tile >= g_ntiles) return;
    int e  = g_tile_e[tile];
    int m0 = g_tile_m0[tile];
    int n0 = blockIdx.x * BN;
    const __half* Wh = (G1 ? g_w1h : g_w2h) + (size_t)e * KTOT * NWID;

    extern __shared__ char smem[];
    uint32_t sb = smem_u32(smem);
    __shared__ int   s_tok[BM];
    __shared__ float s_wt[BM];

    int tid = threadIdx.x, lane = tid & 31, wid = tid >> 5;
    int wm = wid >> 2, wn = wid & 3;   // warp tile: rows wm*64.. , cols wn*64..

    if (tid < BM) { s_tok[tid] = g_tok[m0 + tid]; s_wt[tid] = g_wt[m0 + tid]; }
    __syncthreads();

    // A copy: rows ar, ar+64 (1 uint4 per row at col aq)
    const int aq = tid & 3, ar = tid >> 2;
    // B copy: k-row bk32 = tid>>3 (0..31), segment sg = tid&7 (64B each, 8x64=512B row)
    const int sg = tid & 7, bk32 = tid >> 3;

    const char* aHp[2];
    bool av[2];
#pragma unroll
    for (int r = 0; r < 2; r++) {
        int row = ar + 64 * r;
        if (G1) {
            int tok = s_tok[row];
            av[r] = (tok >= 0);
            aHp[r] = (const char*)g_xh + (size_t)(tok < 0 ? 0 : tok) * KTOT * 2;
        } else {
            av[r] = true;
            aHp[r] = (const char*)g_hh + (size_t)(m0 + row) * KTOT * 2;
        }
    }
    const char* bP = (const char*)(Wh + (size_t)bk32 * NWID + n0 + sg * 32);

    uint4 pah[2], pb[4];
    const uint4 z4 = make_uint4(0, 0, 0, 0);
    const int NCHL = KTOT / BK / SPLIT;
    const int kc0  = (SPLIT > 1) ? blockIdx.z * NCHL : 0;

    auto load_chunk = [&](int kci) {
        size_t ko = (size_t)(kc0 + kci) * 64 + aq * 16;
#pragma unroll
        for (int r = 0; r < 2; r++)
            pah[r] = av[r] ? *(const uint4*)(aHp[r] + ko) : z4;
        const char* bs = bP + (size_t)(kc0 + kci) * BK * NWID * 2;
#pragma unroll
        for (int r = 0; r < 4; r++)
            pb[r] = *(const uint4*)(bs + r * 16);
    };
    auto store_chunk = [&](int buf) {
        uint32_t base = sb + buf * STAGE_SZ;
#pragma unroll
        for (int r = 0; r < 2; r++)
            sts128(base + (uint32_t)(ar + 64 * r) * PA + aq * 16, pah[r]);
        uint32_t boff = base + ST_B + (uint32_t)bk32 * PB + sg * 64;
#pragma unroll
        for (int r = 0; r < 4; r++)
            sts128(boff + r * 16, pb[r]);
    };

    float acc[4][8][4];
#pragma unroll
    for (int i = 0; i < 4; i++)
#pragma unroll
        for (int j = 0; j < 8; j++)
#pragma unroll
            for (int k = 0; k < 4; k++) acc[i][j][k] = 0.f;

    load_chunk(0);
    store_chunk(0);
    __syncthreads();

#pragma unroll 1
    for (int kc = 0; kc < NCHL; kc++) {
        bool more = (kc + 1 < NCHL);
        if (more) load_chunk(kc + 1);

        uint32_t base = sb + (kc & 1) * STAGE_SZ;
#pragma unroll
        for (int kf = 0; kf < 2; kf++) {
            uint32_t ah[4][4], bh[8][2];
#pragma unroll
            for (int mf = 0; mf < 4; mf++) {
                uint32_t arr = wm * 64 + mf * 16 + (lane & 15);
                ldsm4(ah[mf], base + arr * PA + kf * 32 + ((lane >> 4) << 4));
            }
#pragma unroll
            for (int p = 0; p < 4; p++) {
                uint32_t kr = kf * 16 + (lane & 15);
                uint32_t boff = kr * PB + (wn * 64 + p * 16 + ((lane >> 4) << 3)) * 2;
                uint32_t t[4];
                ldsm4t(t, base + ST_B + boff);
                bh[2 * p][0] = t[0]; bh[2 * p][1] = t[1];
                bh[2 * p + 1][0] = t[2]; bh[2 * p + 1][1] = t[3];
            }
#pragma unroll
            for (int mf = 0; mf < 4; mf++)
#pragma unroll
                for (int nf = 0; nf < 8; nf++)
                    mma16816(acc[mf][nf], ah[mf], bh[nf]);
        }
        if (more) store_chunk((kc + 1) & 1);
        __syncthreads();
    }

    // ---- epilogue ----
    int rb = wm * 64 + (lane >> 2);
    int cb = wn * 64 + (lane & 3) * 2;
    const float* be = bias + (size_t)e * NWID + n0;
    bool addb = (SPLIT == 1) || (blockIdx.z == 0);
#pragma unroll
    for (int mf = 0; mf < 4; mf++) {
#pragma unroll
        for (int h = 0; h < 2; h++) {
            int mloc = rb + mf * 16 + h * 8;
            int m = m0 + mloc;
            if (G1) {
                __half2* hrow = (__half2*)(g_hh + (size_t)m * NWID + n0);
#pragma unroll
                for (int nf = 0; nf < 8; nf++) {
                    int c = cb + nf * 8;
                    float2 bb = *(const float2*)(be + c);
                    float v0 = gelu_erf(acc[mf][nf][2 * h + 0] + bb.x);
                    float v1 = gelu_erf(acc[mf][nf][2 * h + 1] + bb.y);
                    hrow[c >> 1] = __floats2half2_rn(v0, v1);
                }
            } else {
                float wt = s_wt[mloc];
                if (wt != 0.f) {
                    int tok = s_tok[mloc];
                    float* orow = out + (size_t)tok * NWID + n0;
#pragma unroll
                    for (int nf = 0; nf < 8; nf++) {
                        int c = cb + nf * 8;
                        float bx = addb ? be[c] : 0.f, by = addb ? be[c + 1] : 0.f;
                        atomicAdd(orow + c,     wt * (acc[mf][nf][2 * h + 0] + bx));
                        atomicAdd(orow + c + 1, wt * (acc[mf][nf][2 * h + 1] + by));
                    }
                }
            }
        }
    }
}

// ---------------- launch ----------------
extern "C" void kernel_launch(void* const* d_in, const int* in_sizes, int n_in,
                              void* d_out, int out_size) {
    const float* x      = (const float*)d_in[0];
    const float* gate_w = (const float*)d_in[1];
    const float* w1     = (const float*)d_in[2];
    const float* b1     = (const float*)d_in[3];
    const float* w2     = (const float*)d_in[4];
    const float* b2     = (const float*)d_in[5];
    float* out = (float*)d_out;

    cudaFuncSetAttribute(moe_gemm<true,  D_MODEL, D_HID, 1>,
                         cudaFuncAttributeMaxDynamicSharedMemorySize, SMEM_DYN);
    cudaFuncSetAttribute(moe_gemm<false, D_HID, D_MODEL, 4>,
                         cudaFuncAttributeMaxDynamicSharedMemorySize, SMEM_DYN);

    const int WN4 = NE * D_MODEL * D_HID / 4;   // 4718592
    convert_x_kernel<<<(NTOK * D_MODEL / 4 + 255) / 256, 256>>>(x, out);
    router_kernel<<<NTOK / 8, 256>>>(x, gate_w);
    setup_scatter_kernel<<<1, 256>>>();
    convert_w_kernel<<<(2 * WN4 + 255) / 256, 256>>>(w1, w2, WN4);
    moe_gemm<true,  D_MODEL, D_HID, 1>
        <<<dim3(D_HID / BN, MAXTILES, 1), 256, SMEM_DYN>>>(b1, out);
    moe_gemm<false, D_HID, D_MODEL, 4>
        <<<dim3(D_MODEL / BN, MAXTILES, 4), 256, SMEM_DYN>>>(b2, out);
}

// round 16
// speedup vs baseline: 1.1701x; 1.1416x over previous
#include <cuda_runtime.h>
#include <cuda_fp16.h>
#include <math.h>
#include <stdint.h>

// ---------------- problem constants ----------------
#define D_MODEL 768
#define D_HID   3072
#define NE      8
#define NTOK    2048
#define NASSIGN (NTOK*2)             // 4096
#define BM 128
#define BN 128
#define BK 32
#define MAXM     (NASSIGN + NE*BM)   // 5120
#define MAXTILES (NASSIGN/BM + NE)   // 40

// ---------------- smem layout (bytes, per buffer) ----------------
#define PA 80                        // A row pitch (32 fp16 = 64B data + 16B pad)
#define PB 272                       // B row pitch (128 fp16 = 256B data + 16B pad)
#define ST_B   (128*PA)              // 10240
#define STAGE_SZ (128*PA + 32*PB)    // 18944
#define SMEM_DYN (2*STAGE_SZ)        // 37888  (2 CTAs/SM)

// ---------------- prep-kernel block ranges ----------------
#define WN4  (NE*D_MODEL*D_HID/4)    // 4718592 float4 per weight tensor
#define W1B  (WN4/256)               // 18432 blocks for w1 convert
#define XB   (NTOK*D_MODEL/4/256)    // 1536 blocks for x convert
#define RB   (NTOK/8)                // 256 router blocks
// GEMM1 grid: y < MAXTILES -> gemm tiles; y >= MAXTILES -> w2 convert tail
#define W2Y  64                      // 24*64 blocks convert w2 (grid-stride)

// ---------------- scratch ----------------
__device__ int    g_counts[NE];
__device__ int    g_tile_e[MAXTILES];
__device__ int    g_tile_m0[MAXTILES];
__device__ int    g_ntiles;
__device__ int    g_expert_of[NASSIGN];
__device__ float  g_w_of[NASSIGN];
__device__ int    g_tok[MAXM];
__device__ float  g_wt[MAXM];
__device__ __align__(256) __half g_xh[(size_t)NTOK * D_MODEL];
__device__ __align__(256) __half g_w1h[(size_t)NE * D_MODEL * D_HID];
__device__ __align__(256) __half g_w2h[(size_t)NE * D_HID * D_MODEL];
__device__ __align__(256) __half g_hh[(size_t)MAXM * D_HID];

// ---------------- helpers ----------------
__device__ __forceinline__ uint32_t smem_u32(const void* p) {
    uint32_t a;
    asm("{ .reg .u64 t; cvta.to.shared.u64 t, %1; cvt.u32.u64 %0, t; }" : "=r"(a) : "l"(p));
    return a;
}
__device__ __forceinline__ void sts128(uint32_t addr, uint4 v) {
    asm volatile("st.shared.v4.b32 [%0], {%1, %2, %3, %4};"
                 :: "r"(addr), "r"(v.x), "r"(v.y), "r"(v.z), "r"(v.w) : "memory");
}
__device__ __forceinline__ void ldsm4(uint32_t* r, uint32_t addr) {
    asm volatile("ldmatrix.sync.aligned.m8n8.x4.shared.b16 {%0,%1,%2,%3}, [%4];"
                 : "=r"(r[0]), "=r"(r[1]), "=r"(r[2]), "=r"(r[3]) : "r"(addr));
}
__device__ __forceinline__ void ldsm4t(uint32_t* r, uint32_t addr) {
    asm volatile("ldmatrix.sync.aligned.m8n8.x4.trans.shared.b16 {%0,%1,%2,%3}, [%4];"
                 : "=r"(r[0]), "=r"(r[1]), "=r"(r[2]), "=r"(r[3]) : "r"(addr));
}
__device__ __forceinline__ void mma16816(float* d, const uint32_t* a, const uint32_t* b) {
    asm volatile("mma.sync.aligned.m16n8k16.row.col.f32.f16.f16.f32 "
                 "{%0,%1,%2,%3}, {%4,%5,%6,%7}, {%8,%9}, {%0,%1,%2,%3};"
                 : "+f"(d[0]), "+f"(d[1]), "+f"(d[2]), "+f"(d[3])
                 : "r"(a[0]), "r"(a[1]), "r"(a[2]), "r"(a[3]), "r"(b[0]), "r"(b[1]));
}
__device__ __forceinline__ float gelu_erf(float v) {
    return 0.5f * v * (1.0f + erff(v * 0.7071067811865476f));
}

// ---------------- init: zero router counters ----------------
__global__ void init_kernel() {
    if (threadIdx.x < NE) g_counts[threadIdx.x] = 0;
}

// ---------------- fused prep: w1 convert (DRAM-bound) hides x-convert + router ----------------
__global__ __launch_bounds__(256) void prep_kernel(const float* __restrict__ w1,
                                                   const float* __restrict__ x,
                                                   const float* __restrict__ gate_w,
                                                   float* __restrict__ out) {
    int bx = blockIdx.x, tid = threadIdx.x;
    if (bx < W1B) {
        // ---- w1 -> fp16 ----
        int i = bx * 256 + tid;
        float4 v = ((const float4*)w1)[i];
        ((__half2*)g_w1h)[2 * i]     = __floats2half2_rn(v.x, v.y);
        ((__half2*)g_w1h)[2 * i + 1] = __floats2half2_rn(v.z, v.w);
        return;
    }
    bx -= W1B;
    if (bx < XB) {
        // ---- x -> fp16; zero d_out ----
        int i = bx * 256 + tid;
        float4 v = ((const float4*)x)[i];
        ((__half2*)g_xh)[2 * i]     = __floats2half2_rn(v.x, v.y);
        ((__half2*)g_xh)[2 * i + 1] = __floats2half2_rn(v.z, v.w);
        ((float4*)out)[i] = make_float4(0.f, 0.f, 0.f, 0.f);
        return;
    }
    bx -= XB;
    // ---- router: one warp per token ----
    int warp = (bx * 256 + tid) >> 5;
    int lane = tid & 31;
    if (warp >= NTOK) return;
    const float* xr = x + (size_t)warp * D_MODEL;
    float acc[NE];
#pragma unroll
    for (int e = 0; e < NE; e++) acc[e] = 0.f;
    for (int d = lane; d < D_MODEL; d += 32) {
        float xv = xr[d];
        const float4* gw = (const float4*)(gate_w + (size_t)d * NE);
        float4 a = gw[0], b = gw[1];
        acc[0] = fmaf(xv, a.x, acc[0]); acc[1] = fmaf(xv, a.y, acc[1]);
        acc[2] = fmaf(xv, a.z, acc[2]); acc[3] = fmaf(xv, a.w, acc[3]);
        acc[4] = fmaf(xv, b.x, acc[4]); acc[5] = fmaf(xv, b.y, acc[5]);
        acc[6] = fmaf(xv, b.z, acc[6]); acc[7] = fmaf(xv, b.w, acc[7]);
    }
#pragma unroll
    for (int e = 0; e < NE; e++)
#pragma unroll
        for (int o = 16; o > 0; o >>= 1)
            acc[e] += __shfl_xor_sync(0xffffffffu, acc[e], o);
    if (lane == 0) {
        float mx = acc[0];
#pragma unroll
        for (int e = 1; e < NE; e++) mx = fmaxf(mx, acc[e]);
        float p[NE]; float s = 0.f;
#pragma unroll
        for (int e = 0; e < NE; e++) { p[e] = expf(acc[e] - mx); s += p[e]; }
        float inv = 1.0f / s;
#pragma unroll
        for (int e = 0; e < NE; e++) p[e] *= inv;
        int i0 = 0;
#pragma unroll
        for (int e = 1; e < NE; e++) if (p[e] > p[i0]) i0 = e;
        int i1 = (i0 == 0) ? 1 : 0;
#pragma unroll
        for (int e = 0; e < NE; e++) if (e != i0 && p[e] > p[i1]) i1 = e;
        float w0 = p[i0], w1v = p[i1];
        float isw = 1.0f / (w0 + w1v);
        g_expert_of[warp * 2 + 0] = i0;
        g_expert_of[warp * 2 + 1] = i1;
        g_w_of[warp * 2 + 0] = w0 * isw;
        g_w_of[warp * 2 + 1] = w1v * isw;
        atomicAdd(&g_counts[i0], 1);
        atomicAdd(&g_counts[i1], 1);
    }
}

// ---------------- fused setup + scatter (single block, smem cursors) ----------------
__global__ __launch_bounds__(256) void setup_scatter_kernel() {
    __shared__ int s_cur[NE];
    int tid = threadIdx.x;
    if (tid == 0) {
        int off = 0, t = 0;
        for (int e = 0; e < NE; e++) {
            s_cur[e] = off;
            int nt = (g_counts[e] + BM - 1) / BM;
            for (int i = 0; i < nt; i++) { g_tile_e[t] = e; g_tile_m0[t] = off + i * BM; t++; }
            off += nt * BM;
        }
        g_ntiles = t;
    }
    __syncthreads();
    for (int i = tid; i < MAXM; i += 256) { g_tok[i] = -1; g_wt[i] = 0.f; }
    __syncthreads();
    for (int idx = tid; idx < NASSIGN; idx += 256) {
        int e = g_expert_of[idx];
        int slot = atomicAdd(&s_cur[e], 1);
        g_tok[slot] = idx >> 1;
        g_wt[slot] = g_w_of[idx];
    }
}

// ---------------- grouped GEMM (R13 mainloop); CONV: tail blocks convert w2 ----------------
template<bool G1, int KTOT, int NWID, int SPLIT, bool CONV>
__global__ __launch_bounds__(256) void moe_gemm(const float* __restrict__ w2src,
                                                const float* __restrict__ bias,
                                                float* __restrict__ out) {
    int tile = blockIdx.y;
    if (CONV && tile >= MAXTILES) {
        // ---- w2 -> fp16 (grid-stride over WN4 float4s) ----
        int cb = blockIdx.x + (tile - MAXTILES) * (D_HID / BN);
        const int stride = (D_HID / BN) * W2Y * 256;
        for (int i = cb * 256 + threadIdx.x; i < WN4; i += stride) {
            float4 v = ((const float4*)w2src)[i];
            ((__half2*)g_w2h)[2 * i]     = __floats2half2_rn(v.x, v.y);
            ((__half2*)g_w2h)[2 * i + 1] = __floats2half2_rn(v.z, v.w);
        }
        return;
    }
    if (tile >= g_ntiles) return;
    int e  = g_tile_e[tile];
    int m0 = g_tile_m0[tile];
    int n0 = blockIdx.x * BN;
    const __half* Wh = (G1 ? g_w1h : g_w2h) + (size_t)e * KTOT * NWID;

    extern __shared__ char smem[];
    uint32_t sb = smem_u32(smem);
    __shared__ int   s_tok[BM];
    __shared__ float s_wt[BM];

    int tid = threadIdx.x, lane = tid & 31, wid = tid >> 5;
    int wm = wid >> 2, wn = wid & 3;

    if (tid < BM) { s_tok[tid] = g_tok[m0 + tid]; s_wt[tid] = g_wt[m0 + tid]; }
    __syncthreads();

    const int aq = tid & 3, ar = tid >> 2;
    const int bq = tid & 15, bk = tid >> 4;

    const char* aHp[2];
    bool av[2];
#pragma unroll
    for (int r = 0; r < 2; r++) {
        int row = ar + 64 * r;
        if (G1) {
            int tok = s_tok[row];
            av[r] = (tok >= 0);
            aHp[r] = (const char*)g_xh + (size_t)(tok < 0 ? 0 : tok) * KTOT * 2;
        } else {
            av[r] = true;
            aHp[r] = (const char*)g_hh + (size_t)(m0 + row) * KTOT * 2;
        }
    }
    const char* bp[2];
#pragma unroll
    for (int r = 0; r < 2; r++)
        bp[r] = (const char*)(Wh + (size_t)(bk + 16 * r) * NWID + n0);

    uint4 pah[2], pb[2];
    const uint4 z4 = make_uint4(0, 0, 0, 0);
    const int NCHL = KTOT / BK / SPLIT;
    const int kc0  = (SPLIT > 1) ? blockIdx.z * NCHL : 0;

    auto load_chunk = [&](int kci) {
        size_t ko = (size_t)(kc0 + kci) * 64 + aq * 16;
#pragma unroll
        for (int r = 0; r < 2; r++)
            pah[r] = av[r] ? *(const uint4*)(aHp[r] + ko) : z4;
        size_t kb = (size_t)(kc0 + kci) * BK * NWID * 2 + bq * 16;
#pragma unroll
        for (int r = 0; r < 2; r++)
            pb[r] = *(const uint4*)(bp[r] + kb);
    };
    auto store_chunk = [&](int buf) {
        uint32_t base = sb + buf * STAGE_SZ;
#pragma unroll
        for (int r = 0; r < 2; r++)
            sts128(base + (uint32_t)(ar + 64 * r) * PA + aq * 16, pah[r]);
#pragma unroll
        for (int r = 0; r < 2; r++)
            sts128(base + ST_B + (uint32_t)(bk + 16 * r) * PB + bq * 16, pb[r]);
    };

    float acc[4][4][4];
#pragma unroll
    for (int i = 0; i < 4; i++)
#pragma unroll
        for (int j = 0; j < 4; j++)
#pragma unroll
            for (int k = 0; k < 4; k++) acc[i][j][k] = 0.f;

    load_chunk(0);
    store_chunk(0);
    __syncthreads();

#pragma unroll 1
    for (int kc = 0; kc < NCHL; kc++) {
        bool more = (kc + 1 < NCHL);
        if (more) load_chunk(kc + 1);

        uint32_t base = sb + (kc & 1) * STAGE_SZ;
#pragma unroll
        for (int kf = 0; kf < 2; kf++) {
            uint32_t ah[4][4], bh[4][2];
#pragma unroll
            for (int mf = 0; mf < 4; mf++) {
                uint32_t arr = wm * 64 + mf * 16 + (lane & 15);
                ldsm4(ah[mf], base + arr * PA + kf * 32 + ((lane >> 4) << 4));
            }
#pragma unroll
            for (int p = 0; p < 2; p++) {
                uint32_t kr = kf * 16 + (lane & 15);
                uint32_t boff = kr * PB + (wn * 32 + p * 16 + ((lane >> 4) << 3)) * 2;
                uint32_t t[4];
                ldsm4t(t, base + ST_B + boff);
                bh[2 * p][0] = t[0]; bh[2 * p][1] = t[1];
                bh[2 * p + 1][0] = t[2]; bh[2 * p + 1][1] = t[3];
            }
#pragma unroll
            for (int mf = 0; mf < 4; mf++)
#pragma unroll
                for (int nf = 0; nf < 4; nf++)
                    mma16816(acc[mf][nf], ah[mf], bh[nf]);
        }
        if (more) store_chunk((kc + 1) & 1);
        __syncthreads();
    }

    // ---- epilogue ----
    int rb = wm * 64 + (lane >> 2);
    int cb = wn * 32 + (lane & 3) * 2;
    const float* be = bias + (size_t)e * NWID + n0;
    bool addb = (SPLIT == 1) || (blockIdx.z == 0);
#pragma unroll
    for (int mf = 0; mf < 4; mf++) {
#pragma unroll
        for (int h = 0; h < 2; h++) {
            int mloc = rb + mf * 16 + h * 8;
            int m = m0 + mloc;
            if (G1) {
                __half2* hrow = (__half2*)(g_hh + (size_t)m * NWID + n0);
#pragma unroll
                for (int nf = 0; nf < 4; nf++) {
                    int c = cb + nf * 8;
                    float2 bb = *(const float2*)(be + c);
                    float v0 = gelu_erf(acc[mf][nf][2 * h + 0] + bb.x);
                    float v1 = gelu_erf(acc[mf][nf][2 * h + 1] + bb.y);
                    hrow[c >> 1] = __floats2half2_rn(v0, v1);
                }
            } else {
                float wt = s_wt[mloc];
                if (wt != 0.f) {
                    int tok = s_tok[mloc];
                    float* orow = out + (size_t)tok * NWID + n0;
#pragma unroll
                    for (int nf = 0; nf < 4; nf++) {
                        int c = cb + nf * 8;
                        float bx = addb ? be[c] : 0.f, by = addb ? be[c + 1] : 0.f;
                        atomicAdd(orow + c,     wt * (acc[mf][nf][2 * h + 0] + bx));
                        atomicAdd(orow + c + 1, wt * (acc[mf][nf][2 * h + 1] + by));
                    }
                }
            }
        }
    }
}

// ---------------- launch ----------------
extern "C" void kernel_launch(void* const* d_in, const int* in_sizes, int n_in,
                              void* d_out, int out_size) {
    const float* x      = (const float*)d_in[0];
    const float* gate_w = (const float*)d_in[1];
    const float* w1     = (const float*)d_in[2];
    const float* b1     = (const float*)d_in[3];
    const float* w2     = (const float*)d_in[4];
    const float* b2     = (const float*)d_in[5];
    float* out = (float*)d_out;

    cudaFuncSetAttribute(moe_gemm<true,  D_MODEL, D_HID, 1, true>,
                         cudaFuncAttributeMaxDynamicSharedMemorySize, SMEM_DYN);
    cudaFuncSetAttribute(moe_gemm<false, D_HID, D_MODEL, 4, false>,
                         cudaFuncAttributeMaxDynamicSharedMemorySize, SMEM_DYN);

    init_kernel<<<1, 32>>>();
    prep_kernel<<<W1B + XB + RB, 256>>>(w1, x, gate_w, out);
    setup_scatter_kernel<<<1, 256>>>();
    moe_gemm<true,  D_MODEL, D_HID, 1, true>
        <<<dim3(D_HID / BN, MAXTILES + W2Y, 1), 256, SMEM_DYN>>>(w2, b1, out);
    moe_gemm<false, D_HID, D_MODEL, 4, false>
        <<<dim3(D_MODEL / BN, MAXTILES, 4), 256, SMEM_DYN>>>(w2, b2, out);
}